// round 8
// baseline (speedup 1.0000x reference)
#include <cuda_runtime.h>
#include <cstdint>
#include <cfloat>

#define B 8
#define H 12
#define N 1024
#define D 64
#define K 256
#define NM1 1023
#define KP1 257
#define EPSF 1e-6f
#define HG 4              // head groups
#define HPG 3             // heads per group

// Scratch (no cudaMalloc). Zero-init at load; counters/accumulators self-reset
// every call so graph replays are deterministic.
__device__ float g_cls_part[HG][B * N];   // per-head-group partial cls sums
__device__ float g_denom[B];              // atomic sum; reset by dedup block
__device__ int   g_sampled[B * K];
__device__ int   g_ids[B * KP1];
__device__ int   g_cnt[B];

// ---------------------------------------------------------------------------
// Kernel 1: head-split cls. 8 rows/warp, 4 lanes/row, 3 heads per warp.
// Grid: 512 x 256 = 4096 warps (4 head-groups x B x 128 warps).
// Partial sums stored per head-group (no atomics on g_cls_part); denominator
// accumulated via one red.add per warp (exact *0.25 scale).
// ---------------------------------------------------------------------------
__global__ void cls_kernel(const float* __restrict__ attn,
                           const float* __restrict__ value) {
    int warpid = threadIdx.x >> 5;
    int lane   = threadIdx.x & 31;
    int gw  = blockIdx.x * 8 + warpid;      // 0..4095
    int hg  = gw >> 10;                     // 0..3 head group
    int gw2 = gw & 1023;
    int b   = gw2 >> 7;
    int w   = gw2 & 127;

    int q = lane >> 2;                      // row within warp (0..7)
    int c = lane & 3;                       // chunk within row (0..3)
    int np = w * 8 + q;
    bool valid = (np < NM1);
    int row = valid ? (np + 1) : 1;

    float acc = 0.0f;
#pragma unroll
    for (int hh = 0; hh < HPG; ++hh) {
        int h = hg * HPG + hh;
        const float4* v4 = (const float4*)(value + (((size_t)(b * H + h)) * N + row) * D);
        float s = 0.0f;
#pragma unroll
        for (int kk = 0; kk < 4; ++kk) {
            float4 t = v4[c + 4 * kk];
            s += t.x * t.x + t.y * t.y + t.z * t.z + t.w * t.w;
        }
        s += __shfl_xor_sync(0xFFFFFFFFu, s, 1);
        s += __shfl_xor_sync(0xFFFFFFFFu, s, 2);
        float a = attn[((size_t)(b * H + h)) * ((size_t)N * N) + (size_t)row];
        acc += sqrtf(s) * a;
    }
    if (!valid) acc = 0.0f;
    if (valid && c == 0) g_cls_part[hg][b * N + np] = acc;

    float t = acc;
#pragma unroll
    for (int o = 16; o > 0; o >>= 1) t += __shfl_xor_sync(0xFFFFFFFFu, t, o);
    if (lane == 0) atomicAdd(&g_denom[b], t * 0.25f);
}

// ---------------------------------------------------------------------------
// Kernel 2 (PDL secondary): ratio-space Gumbel argmax + per-batch dedup.
// Phase 1 (independent of cls): load gumbel_u, compute l = -log(u+eps)+eps.
// Then cudaGridDependencySynchronize(), read partials/denom, combine, reduce.
//   argmax_n( pl+g ) == argmax_n( c[n]/l[n] ),  c = cls/denom + eps, both > 0;
//   compare via c*bl > bc*l (no division).
// ---------------------------------------------------------------------------
__global__ void argmax_dedup_kernel(const float* __restrict__ gumbel_u,
                                    float* __restrict__ out, int write_extra,
                                    size_t off_mask, size_t off_ids) {
    int bj  = blockIdx.x;            // 0 .. B*K-1
    int b   = bj / K;
    int tid = threadIdx.x;           // 128

    const float* gu = gumbel_u + (size_t)bj * NM1;

    // ---- phase 1: gumbel transform (independent of predecessor) ----
    float lv[8];
#pragma unroll
    for (int i = 0; i < 8; ++i) {
        int n = tid + i * 128;
        float u = (n < NM1) ? gu[n] : 0.5f;
        lv[i] = -logf(u + EPSF) + EPSF;
    }

    // ---- wait for cls results ----
    cudaGridDependencySynchronize();

    const float* p0 = g_cls_part[0] + b * N;
    const float* p1 = g_cls_part[1] + b * N;
    const float* p2 = g_cls_part[2] + b * N;
    const float* p3 = g_cls_part[3] + b * N;
    float invd = 1.0f / (g_denom[b] + EPSF);

    float bc = 0.0f, bl = 1.0f;
    int bidx = 0x7FFFFFFF;
#pragma unroll
    for (int i = 0; i < 8; ++i) {
        int n = tid + i * 128;
        if (n < NM1) {
            float l = lv[i];
            float cls = (p0[n] + p1[n]) + (p2[n] + p3[n]);
            float c = fmaf(cls, invd, EPSF);
            float lhs = c * bl, rhs = bc * l;
            if (lhs > rhs || (lhs == rhs && n < bidx)) { bc = c; bl = l; bidx = n; }
        }
    }

    __shared__ float svc[128];
    __shared__ float svl[128];
    __shared__ int   si[128];
    svc[tid] = bc; svl[tid] = bl; si[tid] = bidx;
    __syncthreads();
#pragma unroll
    for (int s = 64; s > 0; s >>= 1) {
        if (tid < s) {
            float c2 = svc[tid + s], l2 = svl[tid + s]; int i2 = si[tid + s];
            float lhs = c2 * svl[tid], rhs = svc[tid] * l2;
            if (lhs > rhs || (lhs == rhs && i2 < si[tid])) {
                svc[tid] = c2; svl[tid] = l2; si[tid] = i2;
            }
        }
        __syncthreads();
    }
    if (tid == 0) g_sampled[bj] = si[0] + 1;

    // ---- last-block-per-batch dedup ----
    __threadfence();
    __shared__ int lastflag;
    if (tid == 0) lastflag = (atomicAdd(&g_cnt[b], 1) == K - 1);
    __syncthreads();
    if (!lastflag) return;
    if (tid == 0) { g_cnt[b] = 0; g_denom[b] = 0.0f; }   // self-reset
    __threadfence();

    __shared__ unsigned int bits[32];
    if (tid < 32) {
        int lane = tid;
        bits[lane] = 0u;
        __syncwarp();
        for (int i = lane; i < K; i += 32) {
            int s = g_sampled[b * K + i];      // 1..1023
            atomicOr(&bits[s >> 5], 1u << (s & 31));
        }
        __syncwarp();

        unsigned int myword = bits[lane];
        int cnt = __popc(myword);
        int incl = cnt;
#pragma unroll
        for (int o = 1; o < 32; o <<= 1) {
            int t = __shfl_up_sync(0xFFFFFFFFu, incl, o);
            if (lane >= o) incl += t;
        }
        int U = __shfl_sync(0xFFFFFFFFu, incl, 31);
        int excl = incl - cnt;
        int zeros = KP1 - U;

        for (int t = lane; t < zeros; t += 32) g_ids[b * KP1 + t] = 0;

        int pos = zeros + excl;
        unsigned int m = myword;
        while (m) {
            int p = __ffs(m) - 1;
            m &= m - 1;
            g_ids[b * KP1 + pos] = lane * 32 + p;
            pos++;
        }
        __syncwarp();

        if (write_extra) {
            for (int t = lane; t < KP1; t += 32) {
                int idv = g_ids[b * KP1 + t];
                out[off_mask + (size_t)b * KP1 + t] = (t == 0 || idv != 0) ? 1.0f : 0.0f;
                out[off_ids  + (size_t)b * KP1 + t] = (float)idv;
            }
        }
    }
}

// ---------------------------------------------------------------------------
// Kernel 3 (PDL secondary): row gather, 12-way ILP. Block = one (b, j).
// ---------------------------------------------------------------------------
__global__ void gather_kernel(const float* __restrict__ attn,
                              float* __restrict__ out) {
    cudaGridDependencySynchronize();

    int j = blockIdx.x;                  // 0..256
    int b = blockIdx.y;                  // 0..7
    int t = threadIdx.x;                 // 0..255
    int id = g_ids[b * KP1 + j];

    float4 v[H];
#pragma unroll
    for (int h = 0; h < H; ++h) {
        const float4* src = (const float4*)(attn + (((size_t)(b * H + h)) * N + id) * N);
        v[h] = __ldg(src + t);
    }
#pragma unroll
    for (int h = 0; h < H; ++h) {
        float4* dst = (float4*)(out + (((size_t)(b * H + h)) * KP1 + j) * N);
        __stcs(dst + t, v[h]);
    }
}

// ---------------------------------------------------------------------------
extern "C" void kernel_launch(void* const* d_in, const int* in_sizes, int n_in,
                              void* d_out, int out_size) {
    const float* attn     = (const float*)d_in[0];
    const float* value    = (const float*)d_in[1];
    const float* gumbel_u = (const float*)d_in[3];
    float* out = (float*)d_out;

    const size_t ATTN_OUT = (size_t)B * H * KP1 * N;     // 25,276,416
    const size_t MASK_OUT = (size_t)B * KP1;             // 2,056
    const size_t TOTAL    = ATTN_OUT + 2 * MASK_OUT;
    int write_extra = ((size_t)out_size >= TOTAL) ? 1 : 0;

    cls_kernel<<<512, 256>>>(attn, value);

    // argmax: PDL overlap with cls (phase 1 independent)
    {
        cudaLaunchConfig_t cfg = {};
        cfg.gridDim  = dim3(B * K, 1, 1);
        cfg.blockDim = dim3(128, 1, 1);
        cfg.stream   = 0;
        cudaLaunchAttribute at[1];
        at[0].id = cudaLaunchAttributeProgrammaticStreamSerialization;
        at[0].val.programmaticStreamSerializationAllowed = 1;
        cfg.attrs = at; cfg.numAttrs = 1;
        cudaLaunchKernelEx(&cfg, argmax_dedup_kernel, gumbel_u, out, write_extra,
                           ATTN_OUT, ATTN_OUT + MASK_OUT);
    }

    // gather: PDL to shave the launch gap (syncs before reading ids)
    {
        cudaLaunchConfig_t cfg = {};
        cfg.gridDim  = dim3(KP1, B, 1);
        cfg.blockDim = dim3(256, 1, 1);
        cfg.stream   = 0;
        cudaLaunchAttribute at[1];
        at[0].id = cudaLaunchAttributeProgrammaticStreamSerialization;
        at[0].val.programmaticStreamSerializationAllowed = 1;
        cfg.attrs = at; cfg.numAttrs = 1;
        cudaLaunchKernelEx(&cfg, gather_kernel, attn, out);
    }
}

// round 9
// speedup vs baseline: 1.0151x; 1.0151x over previous
#include <cuda_runtime.h>
#include <cstdint>
#include <cfloat>

#define B 8
#define H 12
#define N 1024
#define D 64
#define K 256
#define NM1 1023
#define KP1 257
#define EPSF 1e-6f

#define AM_BLOCKS (B * K)              // 2048 argmax blocks
#define GA_PER_BATCH (KP1 * 2)         // 514 gather blocks per batch
#define GA_BLOCKS (B * GA_PER_BATCH)   // 4112

// Scratch (no cudaMalloc). Zero-init at load; all counters/flags self-reset
// within each call so graph replays are deterministic.
__device__ float g_cls[B * N];
__device__ float g_denom[B];          // atomic sum; reset by dedup
__device__ int   g_sampled[B * K];
__device__ int   g_ids[B * KP1];
__device__ int   g_cnt[B];            // argmax completion counters
__device__ int   g_ready[B];          // per-batch ids-ready flags
__device__ int   g_gdone[B];          // gather completion counters

// ---------------------------------------------------------------------------
// Kernel 1: cls_attn[b,n'] = sum_h attn[b,h,0,1+n'] * ||value[b,h,1+n',:]||
// 8 rows/warp, 4 lanes/row (4x float4 each) — measured-best variant.
// One red.add per warp for the denominator (exact *0.25 scale).
// Grid: 128 x 256.
// ---------------------------------------------------------------------------
__global__ void cls_kernel(const float* __restrict__ attn,
                           const float* __restrict__ value) {
    int warpid = threadIdx.x >> 5;
    int lane   = threadIdx.x & 31;
    int gw = blockIdx.x * 8 + warpid;       // 0..1023
    int b  = gw >> 7;
    int w  = gw & 127;

    int q = lane >> 2;                      // row within warp (0..7)
    int c = lane & 3;                       // chunk within row (0..3)
    int np = w * 8 + q;
    bool valid = (np < NM1);
    int row = valid ? (np + 1) : 1;

    float acc = 0.0f;
#pragma unroll
    for (int h = 0; h < H; ++h) {
        const float4* v4 = (const float4*)(value + (((size_t)(b * H + h)) * N + row) * D);
        float s = 0.0f;
#pragma unroll
        for (int kk = 0; kk < 4; ++kk) {
            float4 t = v4[c + 4 * kk];
            s += t.x * t.x + t.y * t.y + t.z * t.z + t.w * t.w;
        }
        s += __shfl_xor_sync(0xFFFFFFFFu, s, 1);
        s += __shfl_xor_sync(0xFFFFFFFFu, s, 2);
        float a = attn[((size_t)(b * H + h)) * ((size_t)N * N) + (size_t)row];
        acc += sqrtf(s) * a;
    }
    if (!valid) acc = 0.0f;
    if (valid && c == 0) g_cls[b * N + np] = acc;

    float t = acc;
#pragma unroll
    for (int o = 16; o > 0; o >>= 1) t += __shfl_xor_sync(0xFFFFFFFFu, t, o);
    if (lane == 0) atomicAdd(&g_denom[b], t * 0.25f);
}

// ---------------------------------------------------------------------------
// Kernel 2 (PDL secondary, FUSED): argmax + dedup + gather in one grid.
//   bid <  2048 : argmax block (bj = bid). Phase 1 (gumbel logf) overlaps cls;
//                 grid-dep-sync; ratio-space argmax; last block per batch runs
//                 bitmap dedup, sets g_ready[b] (release).
//   bid >= 2048 : gather block. Spins on its batch's g_ready flag (acquire),
//                 then copies 12 head-rows (6-head register batches).
// Per-batch flags let batch-b gather overlap later batches' argmax.
// Scheduler dispatches ascending bid -> argmax blocks always have priority.
// ---------------------------------------------------------------------------
__global__ void __launch_bounds__(128)
fused_kernel(const float* __restrict__ gumbel_u,
             const float* __restrict__ attn,
             float* __restrict__ out, int write_extra,
             size_t off_mask, size_t off_ids) {
    int bid = blockIdx.x;
    int tid = threadIdx.x;               // 128

    if (bid < AM_BLOCKS) {
        // ================= argmax path =================
        int bj = bid;
        int b  = bj / K;
        const float* gu = gumbel_u + (size_t)bj * NM1;

        // ---- phase 1: gumbel transform (independent of cls) ----
        float lv[8];
#pragma unroll
        for (int i = 0; i < 8; ++i) {
            int n = tid + i * 128;
            float u = (n < NM1) ? gu[n] : 0.5f;
            lv[i] = -logf(u + EPSF) + EPSF;
        }

        cudaGridDependencySynchronize();

        const float* cls = g_cls + b * N;
        float invd = 1.0f / (g_denom[b] + EPSF);

        // argmax_n(pl+g) == argmax_n(c/l); compare via c*bl > bc*l.
        float bc = 0.0f, bl = 1.0f;
        int bidx = 0x7FFFFFFF;
#pragma unroll
        for (int i = 0; i < 8; ++i) {
            int n = tid + i * 128;
            if (n < NM1) {
                float l = lv[i];
                float c = fmaf(cls[n], invd, EPSF);
                float lhs = c * bl, rhs = bc * l;
                if (lhs > rhs || (lhs == rhs && n < bidx)) { bc = c; bl = l; bidx = n; }
            }
        }

        __shared__ float svc[128];
        __shared__ float svl[128];
        __shared__ int   si[128];
        svc[tid] = bc; svl[tid] = bl; si[tid] = bidx;
        __syncthreads();
#pragma unroll
        for (int s = 64; s > 0; s >>= 1) {
            if (tid < s) {
                float c2 = svc[tid + s], l2 = svl[tid + s]; int i2 = si[tid + s];
                float lhs = c2 * svl[tid], rhs = svc[tid] * l2;
                if (lhs > rhs || (lhs == rhs && i2 < si[tid])) {
                    svc[tid] = c2; svl[tid] = l2; si[tid] = i2;
                }
            }
            __syncthreads();
        }
        if (tid == 0) g_sampled[bj] = si[0] + 1;

        // ---- last-block-per-batch dedup ----
        __threadfence();
        __shared__ int lastflag;
        if (tid == 0) lastflag = (atomicAdd(&g_cnt[b], 1) == K - 1);
        __syncthreads();
        if (!lastflag) return;
        if (tid == 0) { g_cnt[b] = 0; g_denom[b] = 0.0f; }   // self-reset
        __threadfence();

        __shared__ unsigned int bits[32];
        if (tid < 32) {
            int lane = tid;
            bits[lane] = 0u;
            __syncwarp();
            for (int i = lane; i < K; i += 32) {
                int s = g_sampled[b * K + i];      // 1..1023
                atomicOr(&bits[s >> 5], 1u << (s & 31));
            }
            __syncwarp();

            unsigned int myword = bits[lane];
            int cnt = __popc(myword);
            int incl = cnt;
#pragma unroll
            for (int o = 1; o < 32; o <<= 1) {
                int t = __shfl_up_sync(0xFFFFFFFFu, incl, o);
                if (lane >= o) incl += t;
            }
            int U = __shfl_sync(0xFFFFFFFFu, incl, 31);
            int excl = incl - cnt;
            int zeros = KP1 - U;

            for (int t = lane; t < zeros; t += 32) g_ids[b * KP1 + t] = 0;

            int pos = zeros + excl;
            unsigned int m = myword;
            while (m) {
                int p = __ffs(m) - 1;
                m &= m - 1;
                g_ids[b * KP1 + pos] = lane * 32 + p;
                pos++;
            }

            // release: every lane fences its g_ids stores, then lane 0 sets flag
            __threadfence();
            __syncwarp();
            if (lane == 0) *((volatile int*)&g_ready[b]) = 1;

            if (write_extra) {
                for (int t = lane; t < KP1; t += 32) {
                    int idv = g_ids[b * KP1 + t];
                    out[off_mask + (size_t)b * KP1 + t] = (t == 0 || idv != 0) ? 1.0f : 0.0f;
                    out[off_ids  + (size_t)b * KP1 + t] = (float)idv;
                }
            }
        }
    } else {
        // ================= gather path =================
        cudaGridDependencySynchronize();

        int g    = bid - AM_BLOCKS;      // 0..4111
        int b    = g & 7;                // batch-interleaved for pipelining
        int jh   = g >> 3;               // 0..513
        int j    = jh >> 1;              // 0..256
        int half = jh & 1;

        // acquire: spin on this batch's ready flag
        if (tid == 0) {
            while (*((volatile int*)&g_ready[b]) == 0) __nanosleep(64);
        }
        __syncthreads();
        __threadfence();

        int id = g_ids[b * KP1 + j];
        int t  = half * 128 + tid;       // 0..255 float4 index within row

#pragma unroll
        for (int h0 = 0; h0 < H; h0 += 6) {
            float4 v[6];
#pragma unroll
            for (int hh = 0; hh < 6; ++hh) {
                const float4* src = (const float4*)(attn + (((size_t)(b * H + h0 + hh)) * N + id) * N);
                v[hh] = __ldg(src + t);
            }
#pragma unroll
            for (int hh = 0; hh < 6; ++hh) {
                float4* dst = (float4*)(out + (((size_t)(b * H + h0 + hh)) * KP1 + j) * N);
                __stcs(dst + t, v[hh]);
            }
        }

        // last gather block per batch resets flag + counter for next replay
        if (tid == 0) {
            int d = atomicAdd(&g_gdone[b], 1);
            if (d == GA_PER_BATCH - 1) {
                g_gdone[b] = 0;
                *((volatile int*)&g_ready[b]) = 0;
            }
        }
    }
}

// ---------------------------------------------------------------------------
extern "C" void kernel_launch(void* const* d_in, const int* in_sizes, int n_in,
                              void* d_out, int out_size) {
    const float* attn     = (const float*)d_in[0];
    const float* value    = (const float*)d_in[1];
    const float* gumbel_u = (const float*)d_in[3];
    float* out = (float*)d_out;

    const size_t ATTN_OUT = (size_t)B * H * KP1 * N;     // 25,276,416
    const size_t MASK_OUT = (size_t)B * KP1;             // 2,056
    const size_t TOTAL    = ATTN_OUT + 2 * MASK_OUT;
    int write_extra = ((size_t)out_size >= TOTAL) ? 1 : 0;

    cls_kernel<<<128, 256>>>(attn, value);

    // fused argmax+dedup+gather: PDL overlap with cls
    {
        cudaLaunchConfig_t cfg = {};
        cfg.gridDim  = dim3(AM_BLOCKS + GA_BLOCKS, 1, 1);
        cfg.blockDim = dim3(128, 1, 1);
        cfg.stream   = 0;
        cudaLaunchAttribute at[1];
        at[0].id = cudaLaunchAttributeProgrammaticStreamSerialization;
        at[0].val.programmaticStreamSerializationAllowed = 1;
        cfg.attrs = at; cfg.numAttrs = 1;
        cudaLaunchKernelEx(&cfg, fused_kernel, gumbel_u, attn, out, write_extra,
                           ATTN_OUT, ATTN_OUT + MASK_OUT);
    }
}